// round 9
// baseline (speedup 1.0000x reference)
#include <cuda_runtime.h>

#define NN 100000
#define NE 1600000
#define HID 64

// ---------------- scratch (device globals; no runtime allocation) ----------
__device__ __align__(16) int   g_cnt[NN];
__device__ __align__(16) int   g_rowptr[NN + 1];
__device__ __align__(16) int   g_wp[NN];
__device__ __align__(16) int   g_esrc[NE];
__device__ int   g_btot[32];
__device__ int   g_boff[32];
__device__ float g_h1[(size_t)NN * HID];
__device__ float g_h2[(size_t)NN * HID];
__device__ float g_u[(size_t)NN * HID];
__device__ float g_v[(size_t)NN * HID];

// ---------------- packed f32x2 helper --------------------------------------
__device__ __forceinline__ unsigned long long ffma2(unsigned long long a,
                                                    unsigned long long b,
                                                    unsigned long long c) {
    unsigned long long d;
    asm("fma.rn.f32x2 %0, %1, %2, %3;" : "=l"(d) : "l"(a), "l"(b), "l"(c));
    return d;
}

// ---------------- CSR build -------------------------------------------------
__global__ void zero_cnt_kernel() {
    int i = blockIdx.x * blockDim.x + threadIdx.x;
    if (i < NN) g_cnt[i] = 0;
}

__global__ void hist_kernel(const int* __restrict__ dst) {
    int e = blockIdx.x * blockDim.x + threadIdx.x;
    if (e < NE) atomicAdd(&g_cnt[dst[e]], 1);
}

// 3-phase scan: 25 blocks x 4096 elements (int4 per thread)
__global__ void scan_local_kernel() {
    __shared__ int wsum[32];
    int tid = threadIdx.x;
    int lane = tid & 31, wid = tid >> 5;
    int base = blockIdx.x * 4096 + tid * 4;
    int4 v = make_int4(0, 0, 0, 0);
    if (base < NN) v = *(const int4*)&g_cnt[base];
    int s3 = v.x + v.y + v.z + v.w;
    int x = s3;
    #pragma unroll
    for (int o = 1; o < 32; o <<= 1) {
        int t = __shfl_up_sync(0xffffffffu, x, o);
        if (lane >= o) x += t;
    }
    if (lane == 31) wsum[wid] = x;
    __syncthreads();
    if (wid == 0) {
        int ws = wsum[lane];
        #pragma unroll
        for (int o = 1; o < 32; o <<= 1) {
            int t = __shfl_up_sync(0xffffffffu, ws, o);
            if (lane >= o) ws += t;
        }
        wsum[lane] = ws;
    }
    __syncthreads();
    int excl = (x - s3) + (wid > 0 ? wsum[wid - 1] : 0);
    if (base < NN) {
        int4 r;
        r.x = excl;
        r.y = r.x + v.x;
        r.z = r.y + v.y;
        r.w = r.z + v.z;
        *(int4*)&g_rowptr[base] = r;
    }
    if (tid == 0) g_btot[blockIdx.x] = wsum[31];
}

__global__ void scan_spine_kernel() {
    int t = threadIdx.x;
    int v = (t < 25) ? g_btot[t] : 0;
    int x = v;
    #pragma unroll
    for (int o = 1; o < 32; o <<= 1) {
        int tt = __shfl_up_sync(0xffffffffu, x, o);
        if (t >= o) x += tt;
    }
    if (t < 25) g_boff[t] = x - v;
    if (t == 0) g_rowptr[NN] = NE;
}

__global__ void scan_add_kernel() {
    int base = blockIdx.x * 4096 + threadIdx.x * 4;
    if (base < NN) {
        int off = g_boff[blockIdx.x];
        int4 r = *(const int4*)&g_rowptr[base];
        r.x += off; r.y += off; r.z += off; r.w += off;
        *(int4*)&g_rowptr[base] = r;
        *(int4*)&g_wp[base] = r;
    }
}

__global__ void fill_kernel(const int* __restrict__ src, const int* __restrict__ dst) {
    int e = blockIdx.x * blockDim.x + threadIdx.x;
    if (e < NE) {
        int pos = atomicAdd(&g_wp[dst[e]], 1);
        g_esrc[pos] = src[e];
    }
}

// ---------------- fused layer: mean-agg + SAGE linear (+ optional U/V) ------
// Persistent grid-stride warps. Weights staged to shared ONCE per block.
// Warp aggregates mean into registers, then does the 64-wide GEMM via shfl
// broadcast of register-resident mean/h against shared weights.
// UV variant additionally computes U = h3@W1a + b1, V = h3@W1b per node.
template <int FIN, bool RELU, bool UV>
__global__ __launch_bounds__(256)
void fused_layer_kernel(const float* __restrict__ hin,
                        const float* __restrict__ Wl,
                        const float* __restrict__ bl,
                        const float* __restrict__ Wr,
                        const float* __restrict__ Wuv,
                        const float* __restrict__ buv,
                        float* __restrict__ hout,
                        float* __restrict__ uout,
                        float* __restrict__ vout) {
    extern __shared__ float4 sdyn[];
    float4* sW = sdyn;               // [FIN][32]: (Wl[k][j],Wr[k][j],Wl[k][j+32],Wr[k][j+32])
    float4* sU = sdyn + FIN * 32;    // [64][32] when UV: (W1a[k][j],W1b[k][j],W1a[k][j+32],W1b[k][j+32])
    for (int idx = threadIdx.x; idx < FIN * 32; idx += blockDim.x) {
        int k = idx >> 5, j = idx & 31;
        sW[idx] = make_float4(Wl[k * 64 + j], Wr[k * 64 + j],
                              Wl[k * 64 + j + 32], Wr[k * 64 + j + 32]);
    }
    if (UV) {
        for (int idx = threadIdx.x; idx < 64 * 32; idx += blockDim.x) {
            int k = idx >> 5, j = idx & 31;
            sU[idx] = make_float4(Wuv[k * 64 + j], Wuv[(64 + k) * 64 + j],
                                  Wuv[k * 64 + j + 32], Wuv[(64 + k) * 64 + j + 32]);
        }
    }
    __syncthreads();
    int lane = threadIdx.x & 31;
    float b0 = __ldg(bl + lane), b1r = __ldg(bl + lane + 32);
    float bu0 = 0.f, bu1 = 0.f;
    if (UV) { bu0 = __ldg(buv + lane); bu1 = __ldg(buv + lane + 32); }
    int wglob = (blockIdx.x * blockDim.x + threadIdx.x) >> 5;
    int nw = (gridDim.x * blockDim.x) >> 5;

    for (int node = wglob; node < NN; node += nw) {
        int beg = g_rowptr[node];
        int end = g_rowptr[node + 1];
        int deg = end - beg;
        float inv = 1.0f / (float)(deg > 0 ? deg : 1);

        float a0m, a0h, a1m, a1h;
        a0m = b0; a0h = 0.f; a1m = b1r; a1h = 0.f;

        if (FIN == 64) {
            // ---- aggregate (float2 per lane) ----
            float2 q0 = make_float2(0.f, 0.f), q1 = make_float2(0.f, 0.f);
            float2 q2 = make_float2(0.f, 0.f), q3 = make_float2(0.f, 0.f);
            const float2* h2p = (const float2*)hin;
            for (int cb = beg; cb < end; cb += 32) {
                int m = min(32, end - cb);
                int sl = g_esrc[cb + ((lane < m) ? lane : 0)];
                int j = 0;
                for (; j + 4 <= m; j += 4) {
                    int s0 = __shfl_sync(0xffffffffu, sl, j);
                    int s1 = __shfl_sync(0xffffffffu, sl, j + 1);
                    int s2 = __shfl_sync(0xffffffffu, sl, j + 2);
                    int s3 = __shfl_sync(0xffffffffu, sl, j + 3);
                    float2 v0 = __ldg(h2p + (size_t)s0 * 32 + lane);
                    float2 v1 = __ldg(h2p + (size_t)s1 * 32 + lane);
                    float2 v2 = __ldg(h2p + (size_t)s2 * 32 + lane);
                    float2 v3 = __ldg(h2p + (size_t)s3 * 32 + lane);
                    q0.x += v0.x; q0.y += v0.y;
                    q1.x += v1.x; q1.y += v1.y;
                    q2.x += v2.x; q2.y += v2.y;
                    q3.x += v3.x; q3.y += v3.y;
                }
                for (; j < m; j++) {
                    int s0 = __shfl_sync(0xffffffffu, sl, j);
                    float2 v0 = __ldg(h2p + (size_t)s0 * 32 + lane);
                    q0.x += v0.x; q0.y += v0.y;
                }
            }
            float2 mac = make_float2(((q0.x + q1.x) + (q2.x + q3.x)) * inv,
                                     ((q0.y + q1.y) + (q2.y + q3.y)) * inv);
            float2 hv2 = __ldg(h2p + (size_t)node * 32 + lane);
            // ---- GEMM via shfl broadcast ----
            #pragma unroll
            for (int p = 0; p < 32; p++) {
                float mx = __shfl_sync(0xffffffffu, mac.x, p);
                float my = __shfl_sync(0xffffffffu, mac.y, p);
                float hx = __shfl_sync(0xffffffffu, hv2.x, p);
                float hy = __shfl_sync(0xffffffffu, hv2.y, p);
                float4 w0 = sW[(2 * p) * 32 + lane];
                float4 w1 = sW[(2 * p + 1) * 32 + lane];
                a0m += mx * w0.x; a0h += hx * w0.y;
                a1m += mx * w0.z; a1h += hx * w0.w;
                a0m += my * w1.x; a0h += hy * w1.y;
                a1m += my * w1.z; a1h += hy * w1.w;
            }
        } else {  // FIN == 32: one float per lane
            float q0 = 0.f, q1 = 0.f, q2 = 0.f, q3 = 0.f;
            for (int cb = beg; cb < end; cb += 32) {
                int m = min(32, end - cb);
                int sl = g_esrc[cb + ((lane < m) ? lane : 0)];
                int j = 0;
                for (; j + 4 <= m; j += 4) {
                    int s0 = __shfl_sync(0xffffffffu, sl, j);
                    int s1 = __shfl_sync(0xffffffffu, sl, j + 1);
                    int s2 = __shfl_sync(0xffffffffu, sl, j + 2);
                    int s3 = __shfl_sync(0xffffffffu, sl, j + 3);
                    q0 += __ldg(hin + (size_t)s0 * 32 + lane);
                    q1 += __ldg(hin + (size_t)s1 * 32 + lane);
                    q2 += __ldg(hin + (size_t)s2 * 32 + lane);
                    q3 += __ldg(hin + (size_t)s3 * 32 + lane);
                }
                for (; j < m; j++) {
                    int s0 = __shfl_sync(0xffffffffu, sl, j);
                    q0 += __ldg(hin + (size_t)s0 * 32 + lane);
                }
            }
            float mac = ((q0 + q1) + (q2 + q3)) * inv;
            float hv = __ldg(hin + (size_t)node * 32 + lane);
            #pragma unroll
            for (int p = 0; p < 32; p++) {
                float mv = __shfl_sync(0xffffffffu, mac, p);
                float hb = __shfl_sync(0xffffffffu, hv, p);
                float4 w = sW[p * 32 + lane];
                a0m += mv * w.x; a0h += hb * w.y;
                a1m += mv * w.z; a1h += hb * w.w;
            }
        }

        float a0 = a0m + a0h;
        float a1 = a1m + a1h;
        if (RELU) { a0 = fmaxf(a0, 0.f); a1 = fmaxf(a1, 0.f); }

        if (!UV) {
            hout[(size_t)node * 64 + lane] = a0;
            hout[(size_t)node * 64 + lane + 32] = a1;
        } else {
            // U = h3@W1a + b1, V = h3@W1b   (h3 = a0/a1, register-resident)
            float u0 = bu0, u1 = bu1, v0 = 0.f, v1 = 0.f;
            #pragma unroll
            for (int l = 0; l < 32; l++) {
                float hl = __shfl_sync(0xffffffffu, a0, l);
                float hh = __shfl_sync(0xffffffffu, a1, l);
                float4 wl = sU[l * 32 + lane];
                float4 wh = sU[(l + 32) * 32 + lane];
                u0 += hl * wl.x + hh * wh.x;
                v0 += hl * wl.y + hh * wh.y;
                u1 += hl * wl.z + hh * wh.z;
                v1 += hl * wl.w + hh * wh.w;
            }
            uout[(size_t)node * 64 + lane] = u0;
            uout[(size_t)node * 64 + lane + 32] = u1;
            vout[(size_t)node * 64 + lane] = v0;
            vout[(size_t)node * 64 + lane + 32] = v1;
        }
    }
}

// ---------------- edge MLP: persistent tiles, warp gather + per-thread MLP --
#define EPT 68  // padded row stride in floats
__global__ __launch_bounds__(128)
void edge_kernel(const int* __restrict__ esrc, const int* __restrict__ edst,
                 const float* __restrict__ eattr,
                 const float* __restrict__ W1, const float* __restrict__ W2,
                 const float* __restrict__ b2v, const float* __restrict__ W3,
                 const float* __restrict__ b3v, float* __restrict__ out) {
    __shared__ __align__(16) float tile[128 * EPT];
    __shared__ float  sW1e[64 * 8];   // [j*8 + i] = W1[(128+i)*64 + j]
    __shared__ float2 sW2[64 * 16];   // [j*16 + k] = (W2[j][2k], W2[j][2k+1])
    __shared__ float2 sb2[16];
    __shared__ float  sW3[32];
    __shared__ float  sb3;
    int tid = threadIdx.x, lane = tid & 31, wid = tid >> 5;
    for (int idx = tid; idx < 64 * 8; idx += 128) {
        int j = idx >> 3, i = idx & 7;
        sW1e[idx] = W1[(128 + i) * 64 + j];
    }
    for (int idx = tid; idx < 64 * 16; idx += 128) {
        int j = idx >> 4, k = idx & 15;
        sW2[idx] = make_float2(W2[j * 32 + 2 * k], W2[j * 32 + 2 * k + 1]);
    }
    if (tid < 16) sb2[tid] = make_float2(b2v[2 * tid], b2v[2 * tid + 1]);
    if (tid < 32) sW3[tid] = W3[tid];
    if (tid == 0) sb3 = b3v[0];
    __syncthreads();

    const float2* U2 = (const float2*)g_u;
    const float2* V2 = (const float2*)g_v;
    float* twarp = &tile[(wid * 32) * EPT];
    const float* trow = &tile[tid * EPT];

    for (int ti = blockIdx.x; ti < NE / 128; ti += gridDim.x) {
        int ebase = ti * 128;
        __syncwarp();  // prior iteration's reads complete before overwrite
        // ---- gather: warp handles edges [ebase + wid*32, +32)
        int eg = ebase + wid * 32 + lane;
        int sl = esrc[eg];
        int dl = edst[eg];
        #pragma unroll 4
        for (int j = 0; j < 32; j++) {
            int s = __shfl_sync(0xffffffffu, sl, j);
            int d = __shfl_sync(0xffffffffu, dl, j);
            float2 u = __ldg(U2 + (size_t)s * 32 + lane);
            float2 v = __ldg(V2 + (size_t)d * 32 + lane);
            *(float2*)&twarp[j * EPT + lane * 2] = make_float2(u.x + v.x, u.y + v.y);
        }
        __syncwarp();

        // ---- compute: thread-per-edge
        int e = ebase + tid;
        const float4* ep = (const float4*)eattr + (size_t)e * 2;
        float4 ea0 = __ldg(ep);
        float4 ea1 = __ldg(ep + 1);

        unsigned long long z2[16];
        #pragma unroll
        for (int k = 0; k < 16; k++)
            z2[k] = *((const unsigned long long*)&sb2[k]);

        #pragma unroll
        for (int jv = 0; jv < 16; jv++) {
            float4 uv4 = *(const float4*)(trow + jv * 4);
            float zt[4] = {uv4.x, uv4.y, uv4.z, uv4.w};
            #pragma unroll
            for (int t = 0; t < 4; t++) {
                int j = jv * 4 + t;
                const float* w1 = &sW1e[j * 8];
                float e1 = ea0.x * w1[0] + ea0.y * w1[1] + ea0.z * w1[2] + ea0.w * w1[3]
                         + ea1.x * w1[4] + ea1.y * w1[5] + ea1.z * w1[6] + ea1.w * w1[7];
                float z1 = fmaxf(zt[t] + e1, 0.0f);
                unsigned long long z1p;
                asm("mov.b64 %0, {%1, %1};" : "=l"(z1p) : "f"(z1));
                const unsigned long long* w2 = (const unsigned long long*)&sW2[j * 16];
                #pragma unroll
                for (int k = 0; k < 16; k++) z2[k] = ffma2(z1p, w2[k], z2[k]);
            }
        }

        float acc = sb3;
        #pragma unroll
        for (int k = 0; k < 16; k++) {
            float zx, zy;
            asm("mov.b64 {%0, %1}, %2;" : "=f"(zx), "=f"(zy) : "l"(z2[k]));
            acc += fmaxf(zx, 0.f) * sW3[2 * k] + fmaxf(zy, 0.f) * sW3[2 * k + 1];
        }
        out[e] = 1.0f / (1.0f + __expf(-acc));
    }
}

// ---------------- launch ----------------------------------------------------
extern "C" void kernel_launch(void* const* d_in, const int* in_sizes, int n_in,
                              void* d_out, int out_size) {
    const float* x     = (const float*)d_in[0];
    const int*   eidx  = (const int*)d_in[1];
    const int*   srcv  = eidx;
    const int*   dstv  = eidx + NE;
    const float* eattr = (const float*)d_in[2];
    const float* Wl0 = (const float*)d_in[3];
    const float* bl0 = (const float*)d_in[4];
    const float* Wr0 = (const float*)d_in[5];
    const float* Wl1 = (const float*)d_in[6];
    const float* bl1 = (const float*)d_in[7];
    const float* Wr1 = (const float*)d_in[8];
    const float* Wl2 = (const float*)d_in[9];
    const float* bl2 = (const float*)d_in[10];
    const float* Wr2 = (const float*)d_in[11];
    const float* W1  = (const float*)d_in[12];
    const float* b1  = (const float*)d_in[13];
    const float* W2  = (const float*)d_in[14];
    const float* b2  = (const float*)d_in[15];
    const float* W3  = (const float*)d_in[16];
    const float* b3  = (const float*)d_in[17];
    float* out = (float*)d_out;

    float *p_h1, *p_h2, *p_u, *p_v;
    cudaGetSymbolAddress((void**)&p_h1, g_h1);
    cudaGetSymbolAddress((void**)&p_h2, g_h2);
    cudaGetSymbolAddress((void**)&p_u, g_u);
    cudaGetSymbolAddress((void**)&p_v, g_v);

    // Unconditional (no static guards allowed). Non-stream API; capture-legal.
    cudaFuncSetAttribute(fused_layer_kernel<64, false, true>,
                         cudaFuncAttributeMaxDynamicSharedMemorySize, 66 * 1024);

    const int TB = 256;
    int nb = (NN + TB - 1) / TB;
    int eb = (NE + TB - 1) / TB;

    // CSR build
    zero_cnt_kernel<<<nb, TB>>>();
    hist_kernel<<<eb, TB>>>(dstv);
    scan_local_kernel<<<25, 1024>>>();
    scan_spine_kernel<<<1, 32>>>();
    scan_add_kernel<<<25, 1024>>>();
    fill_kernel<<<eb, TB>>>(srcv, dstv);

    // Layer 0: FIN=32, relu           (smem 16KB, 8 blocks/SM)
    fused_layer_kernel<32, true, false><<<1184, TB, 32 * 32 * 16>>>(
        x, Wl0, bl0, Wr0, nullptr, nullptr, p_h1, nullptr, nullptr);
    // Layer 1: FIN=64, relu           (smem 32KB, 7 blocks/SM)
    fused_layer_kernel<64, true, false><<<1036, TB, 64 * 32 * 16>>>(
        p_h1, Wl1, bl1, Wr1, nullptr, nullptr, p_h2, nullptr, nullptr);
    // Layer 2: FIN=64, no relu, fused U/V   (smem 64KB, 3 blocks/SM)
    fused_layer_kernel<64, false, true><<<444, TB, 128 * 32 * 16>>>(
        p_h2, Wl2, bl2, Wr2, W1, b1, nullptr, p_u, p_v);

    // Edge predictor (persistent tiles; 5 blocks/SM at 45.3KB smem)
    edge_kernel<<<740, 128>>>(srcv, dstv, eattr, W1, W2, b2, W3, b3, out);
}

// round 13
// speedup vs baseline: 1.5723x; 1.5723x over previous
#include <cuda_runtime.h>

#define NN 100000
#define NE 1600000
#define HID 64

// ---------------- scratch (device globals; no runtime allocation) ----------
__device__ __align__(16) int   g_cnt[NN];
__device__ __align__(16) int   g_rowptr[NN + 1];
__device__ __align__(16) int   g_wp[NN];
__device__ __align__(16) int   g_esrc[NE];
__device__ int   g_btot[32];
__device__ int   g_boff[32];
__device__ float g_mean[(size_t)NN * HID];
__device__ float g_h1[(size_t)NN * HID];
__device__ float g_h2[(size_t)NN * HID];
__device__ float g_h3[(size_t)NN * HID];
__device__ float g_u[(size_t)NN * HID];
__device__ float g_v[(size_t)NN * HID];

// ---------------- packed f32x2 helper --------------------------------------
__device__ __forceinline__ unsigned long long ffma2(unsigned long long a,
                                                    unsigned long long b,
                                                    unsigned long long c) {
    unsigned long long d;
    asm("fma.rn.f32x2 %0, %1, %2, %3;" : "=l"(d) : "l"(a), "l"(b), "l"(c));
    return d;
}

// ---------------- CSR build -------------------------------------------------
__global__ void zero_cnt_kernel() {
    int i = blockIdx.x * blockDim.x + threadIdx.x;
    if (i < NN) g_cnt[i] = 0;
}

__global__ void hist_kernel(const int* __restrict__ dst) {
    int e = blockIdx.x * blockDim.x + threadIdx.x;
    if (e < NE) atomicAdd(&g_cnt[dst[e]], 1);
}

// 3-phase scan: 25 blocks x 4096 elements (int4 per thread)
__global__ void scan_local_kernel() {
    __shared__ int wsum[32];
    int tid = threadIdx.x;
    int lane = tid & 31, wid = tid >> 5;
    int base = blockIdx.x * 4096 + tid * 4;
    int4 v = make_int4(0, 0, 0, 0);
    if (base < NN) v = *(const int4*)&g_cnt[base];
    int s3 = v.x + v.y + v.z + v.w;
    int x = s3;
    #pragma unroll
    for (int o = 1; o < 32; o <<= 1) {
        int t = __shfl_up_sync(0xffffffffu, x, o);
        if (lane >= o) x += t;
    }
    if (lane == 31) wsum[wid] = x;
    __syncthreads();
    if (wid == 0) {
        int ws = wsum[lane];
        #pragma unroll
        for (int o = 1; o < 32; o <<= 1) {
            int t = __shfl_up_sync(0xffffffffu, ws, o);
            if (lane >= o) ws += t;
        }
        wsum[lane] = ws;
    }
    __syncthreads();
    int excl = (x - s3) + (wid > 0 ? wsum[wid - 1] : 0);
    if (base < NN) {
        int4 r;
        r.x = excl;
        r.y = r.x + v.x;
        r.z = r.y + v.y;
        r.w = r.z + v.z;
        *(int4*)&g_rowptr[base] = r;
    }
    if (tid == 0) g_btot[blockIdx.x] = wsum[31];
}

__global__ void scan_spine_kernel() {
    int t = threadIdx.x;
    int v = (t < 25) ? g_btot[t] : 0;
    int x = v;
    #pragma unroll
    for (int o = 1; o < 32; o <<= 1) {
        int tt = __shfl_up_sync(0xffffffffu, x, o);
        if (t >= o) x += tt;
    }
    if (t < 25) g_boff[t] = x - v;
    if (t == 0) g_rowptr[NN] = NE;
}

__global__ void scan_add_kernel() {
    int base = blockIdx.x * 4096 + threadIdx.x * 4;
    if (base < NN) {
        int off = g_boff[blockIdx.x];
        int4 r = *(const int4*)&g_rowptr[base];
        r.x += off; r.y += off; r.z += off; r.w += off;
        *(int4*)&g_rowptr[base] = r;
        *(int4*)&g_wp[base] = r;
    }
}

__global__ void fill_kernel(const int* __restrict__ src, const int* __restrict__ dst) {
    int e = blockIdx.x * blockDim.x + threadIdx.x;
    if (e < NE) {
        int pos = atomicAdd(&g_wp[dst[e]], 1);
        g_esrc[pos] = src[e];
    }
}

// ---------------- mean aggregation (warp per node, full occupancy) ----------
template <int F>
__global__ void agg_kernel(const float* __restrict__ h, float* __restrict__ out) {
    int warp = (blockIdx.x * blockDim.x + threadIdx.x) >> 5;
    if (warp >= NN) return;
    int lane = threadIdx.x & 31;
    int beg = g_rowptr[warp];
    int end = g_rowptr[warp + 1];
    int deg = end - beg;
    float inv = 1.0f / (float)(deg > 0 ? deg : 1);
    if (F == 64) {
        float2 a0 = make_float2(0.f, 0.f), a1 = make_float2(0.f, 0.f);
        float2 a2 = make_float2(0.f, 0.f), a3 = make_float2(0.f, 0.f);
        for (int cb = beg; cb < end; cb += 32) {
            int m = min(32, end - cb);
            int sl = g_esrc[cb + ((lane < m) ? lane : 0)];
            int j = 0;
            for (; j + 4 <= m; j += 4) {
                int s0 = __shfl_sync(0xffffffffu, sl, j);
                int s1 = __shfl_sync(0xffffffffu, sl, j + 1);
                int s2 = __shfl_sync(0xffffffffu, sl, j + 2);
                int s3 = __shfl_sync(0xffffffffu, sl, j + 3);
                float2 v0 = __ldg(((const float2*)h) + (size_t)s0 * 32 + lane);
                float2 v1 = __ldg(((const float2*)h) + (size_t)s1 * 32 + lane);
                float2 v2 = __ldg(((const float2*)h) + (size_t)s2 * 32 + lane);
                float2 v3 = __ldg(((const float2*)h) + (size_t)s3 * 32 + lane);
                a0.x += v0.x; a0.y += v0.y;
                a1.x += v1.x; a1.y += v1.y;
                a2.x += v2.x; a2.y += v2.y;
                a3.x += v3.x; a3.y += v3.y;
            }
            for (; j < m; j++) {
                int s0 = __shfl_sync(0xffffffffu, sl, j);
                float2 v0 = __ldg(((const float2*)h) + (size_t)s0 * 32 + lane);
                a0.x += v0.x; a0.y += v0.y;
            }
        }
        float2 r = make_float2(((a0.x + a1.x) + (a2.x + a3.x)) * inv,
                               ((a0.y + a1.y) + (a2.y + a3.y)) * inv);
        ((float2*)out)[(size_t)warp * 32 + lane] = r;
    } else {  // F == 32
        float a0 = 0.f, a1 = 0.f, a2 = 0.f, a3 = 0.f;
        for (int cb = beg; cb < end; cb += 32) {
            int m = min(32, end - cb);
            int sl = g_esrc[cb + ((lane < m) ? lane : 0)];
            int j = 0;
            for (; j + 4 <= m; j += 4) {
                int s0 = __shfl_sync(0xffffffffu, sl, j);
                int s1 = __shfl_sync(0xffffffffu, sl, j + 1);
                int s2 = __shfl_sync(0xffffffffu, sl, j + 2);
                int s3 = __shfl_sync(0xffffffffu, sl, j + 3);
                a0 += __ldg(h + (size_t)s0 * 32 + lane);
                a1 += __ldg(h + (size_t)s1 * 32 + lane);
                a2 += __ldg(h + (size_t)s2 * 32 + lane);
                a3 += __ldg(h + (size_t)s3 * 32 + lane);
            }
            for (; j < m; j++) {
                int s0 = __shfl_sync(0xffffffffu, sl, j);
                a0 += __ldg(h + (size_t)s0 * 32 + lane);
            }
        }
        out[(size_t)warp * 32 + lane] = ((a0 + a1) + (a2 + a3)) * inv;
    }
}

// ---------------- SAGE linear (PERSISTENT grid-stride; weights staged once) -
template <int FIN, bool RELU>
__global__ __launch_bounds__(256)
void sage_gemm_kernel(const float* __restrict__ mean,
                      const float* __restrict__ h,
                      const float* __restrict__ Wl,
                      const float* __restrict__ bl,
                      const float* __restrict__ Wr,
                      float* __restrict__ out) {
    __shared__ float4 sW[FIN][32];  // (Wl[k][j], Wr[k][j], Wl[k][j+32], Wr[k][j+32])
    for (int idx = threadIdx.x; idx < FIN * 32; idx += blockDim.x) {
        int k = idx >> 5, j = idx & 31;
        sW[k][j] = make_float4(Wl[k * 64 + j], Wr[k * 64 + j],
                               Wl[k * 64 + j + 32], Wr[k * 64 + j + 32]);
    }
    __syncthreads();
    int lane = threadIdx.x & 31;
    float b0 = __ldg(bl + lane);
    float b1 = __ldg(bl + lane + 32);
    int wglob = (blockIdx.x * blockDim.x + threadIdx.x) >> 5;
    int nw = (gridDim.x * blockDim.x) >> 5;

    for (int node = wglob; node < NN; node += nw) {
        const float4* mrow = (const float4*)(mean + (size_t)node * FIN);
        const float4* hrow = (const float4*)(h + (size_t)node * FIN);
        float a0 = b0;
        float a1 = b1;
        #pragma unroll 4
        for (int kv = 0; kv < FIN / 4; kv++) {
            float4 m4 = __ldg(mrow + kv);
            float4 h4 = __ldg(hrow + kv);
            {
                float4 w = sW[4 * kv + 0][lane];
                a0 += m4.x * w.x + h4.x * w.y; a1 += m4.x * w.z + h4.x * w.w;
            }
            {
                float4 w = sW[4 * kv + 1][lane];
                a0 += m4.y * w.x + h4.y * w.y; a1 += m4.y * w.z + h4.y * w.w;
            }
            {
                float4 w = sW[4 * kv + 2][lane];
                a0 += m4.z * w.x + h4.z * w.y; a1 += m4.z * w.z + h4.z * w.w;
            }
            {
                float4 w = sW[4 * kv + 3][lane];
                a0 += m4.w * w.x + h4.w * w.y; a1 += m4.w * w.z + h4.w * w.w;
            }
        }
        if (RELU) { a0 = fmaxf(a0, 0.f); a1 = fmaxf(a1, 0.f); }
        out[(size_t)node * 64 + lane] = a0;
        out[(size_t)node * 64 + lane + 32] = a1;
    }
}

// ---------------- U/V precompute (PERSISTENT): U = h3@W1a + b1, V = h3@W1b --
__global__ __launch_bounds__(256)
void uv_kernel(const float* __restrict__ W1, const float* __restrict__ b1) {
    __shared__ float4 sW[64][32];  // (W1a[k][j], W1b[k][j], W1a[k][j+32], W1b[k][j+32])
    for (int idx = threadIdx.x; idx < 64 * 32; idx += blockDim.x) {
        int k = idx >> 5, j = idx & 31;
        sW[k][j] = make_float4(W1[k * 64 + j], W1[(64 + k) * 64 + j],
                               W1[k * 64 + j + 32], W1[(64 + k) * 64 + j + 32]);
    }
    __syncthreads();
    int lane = threadIdx.x & 31;
    float bb0 = __ldg(b1 + lane), bb1 = __ldg(b1 + lane + 32);
    int wglob = (blockIdx.x * blockDim.x + threadIdx.x) >> 5;
    int nw = (gridDim.x * blockDim.x) >> 5;

    for (int node = wglob; node < NN; node += nw) {
        const float4* hrow = (const float4*)(g_h3 + (size_t)node * 64);
        float u0 = bb0, u1 = bb1;
        float v0 = 0.f, v1 = 0.f;
        #pragma unroll 4
        for (int kv = 0; kv < 16; kv++) {
            float4 h4 = __ldg(hrow + kv);
            {
                float4 w = sW[4 * kv + 0][lane];
                u0 += h4.x * w.x; v0 += h4.x * w.y; u1 += h4.x * w.z; v1 += h4.x * w.w;
            }
            {
                float4 w = sW[4 * kv + 1][lane];
                u0 += h4.y * w.x; v0 += h4.y * w.y; u1 += h4.y * w.z; v1 += h4.y * w.w;
            }
            {
                float4 w = sW[4 * kv + 2][lane];
                u0 += h4.z * w.x; v0 += h4.z * w.y; u1 += h4.z * w.z; v1 += h4.z * w.w;
            }
            {
                float4 w = sW[4 * kv + 3][lane];
                u0 += h4.w * w.x; v0 += h4.w * w.y; u1 += h4.w * w.z; v1 += h4.w * w.w;
            }
        }
        g_u[(size_t)node * 64 + lane] = u0;
        g_u[(size_t)node * 64 + lane + 32] = u1;
        g_v[(size_t)node * 64 + lane] = v0;
        g_v[(size_t)node * 64 + lane + 32] = v1;
    }
}

// ---------------- edge MLP (PERSISTENT tiles; single wave at 4 blocks/SM) ---
#define EPT 68  // padded row stride in floats
__global__ __launch_bounds__(128)
void edge_kernel(const int* __restrict__ esrc, const int* __restrict__ edst,
                 const float* __restrict__ eattr,
                 const float* __restrict__ W1, const float* __restrict__ W2,
                 const float* __restrict__ b2v, const float* __restrict__ W3,
                 const float* __restrict__ b3v, float* __restrict__ out) {
    __shared__ __align__(16) float tile[128 * EPT];
    __shared__ float  sW1e[64 * 8];   // [j*8 + i] = W1[(128+i)*64 + j]
    __shared__ float2 sW2[64 * 16];   // [j*16 + k] = (W2[j][2k], W2[j][2k+1])
    __shared__ float2 sb2[16];
    __shared__ float  sW3[32];
    __shared__ float  sb3;
    int tid = threadIdx.x, lane = tid & 31, wid = tid >> 5;
    for (int idx = tid; idx < 64 * 8; idx += 128) {
        int j = idx >> 3, i = idx & 7;
        sW1e[idx] = W1[(128 + i) * 64 + j];
    }
    for (int idx = tid; idx < 64 * 16; idx += 128) {
        int j = idx >> 4, k = idx & 15;
        sW2[idx] = make_float2(W2[j * 32 + 2 * k], W2[j * 32 + 2 * k + 1]);
    }
    if (tid < 16) sb2[tid] = make_float2(b2v[2 * tid], b2v[2 * tid + 1]);
    if (tid < 32) sW3[tid] = W3[tid];
    if (tid == 0) sb3 = b3v[0];
    __syncthreads();

    const float2* U2 = (const float2*)g_u;
    const float2* V2 = (const float2*)g_v;
    float* twarp = &tile[(wid * 32) * EPT];
    const float* trow = &tile[tid * EPT];

    for (int ti = blockIdx.x; ti < NE / 128; ti += gridDim.x) {
        int ebase = ti * 128;
        __syncwarp();  // prior iteration's reads complete before overwrite
        // ---- gather: warp handles edges [ebase + wid*32, +32)
        int eg = ebase + wid * 32 + lane;
        int sl = esrc[eg];
        int dl = edst[eg];
        #pragma unroll 4
        for (int j = 0; j < 32; j++) {
            int s = __shfl_sync(0xffffffffu, sl, j);
            int d = __shfl_sync(0xffffffffu, dl, j);
            float2 u = __ldg(U2 + (size_t)s * 32 + lane);
            float2 v = __ldg(V2 + (size_t)d * 32 + lane);
            *(float2*)&twarp[j * EPT + lane * 2] = make_float2(u.x + v.x, u.y + v.y);
        }
        __syncwarp();

        // ---- compute: thread-per-edge
        int e = ebase + tid;
        const float4* ep = (const float4*)eattr + (size_t)e * 2;
        float4 ea0 = __ldg(ep);
        float4 ea1 = __ldg(ep + 1);

        unsigned long long z2[16];
        #pragma unroll
        for (int k = 0; k < 16; k++)
            z2[k] = *((const unsigned long long*)&sb2[k]);

        #pragma unroll
        for (int jv = 0; jv < 16; jv++) {
            float4 uv4 = *(const float4*)(trow + jv * 4);
            float zt[4] = {uv4.x, uv4.y, uv4.z, uv4.w};
            #pragma unroll
            for (int t = 0; t < 4; t++) {
                int j = jv * 4 + t;
                const float* w1 = &sW1e[j * 8];
                float e1 = ea0.x * w1[0] + ea0.y * w1[1] + ea0.z * w1[2] + ea0.w * w1[3]
                         + ea1.x * w1[4] + ea1.y * w1[5] + ea1.z * w1[6] + ea1.w * w1[7];
                float z1 = fmaxf(zt[t] + e1, 0.0f);
                unsigned long long z1p;
                asm("mov.b64 %0, {%1, %1};" : "=l"(z1p) : "f"(z1));
                const unsigned long long* w2 = (const unsigned long long*)&sW2[j * 16];
                #pragma unroll
                for (int k = 0; k < 16; k++) z2[k] = ffma2(z1p, w2[k], z2[k]);
            }
        }

        float acc = sb3;
        #pragma unroll
        for (int k = 0; k < 16; k++) {
            float zx, zy;
            asm("mov.b64 {%0, %1}, %2;" : "=f"(zx), "=f"(zy) : "l"(z2[k]));
            acc += fmaxf(zx, 0.f) * sW3[2 * k] + fmaxf(zy, 0.f) * sW3[2 * k + 1];
        }
        out[e] = 1.0f / (1.0f + __expf(-acc));
    }
}

// ---------------- launch ----------------------------------------------------
extern "C" void kernel_launch(void* const* d_in, const int* in_sizes, int n_in,
                              void* d_out, int out_size) {
    const float* x     = (const float*)d_in[0];
    const int*   eidx  = (const int*)d_in[1];
    const int*   srcv  = eidx;
    const int*   dstv  = eidx + NE;
    const float* eattr = (const float*)d_in[2];
    const float* Wl0 = (const float*)d_in[3];
    const float* bl0 = (const float*)d_in[4];
    const float* Wr0 = (const float*)d_in[5];
    const float* Wl1 = (const float*)d_in[6];
    const float* bl1 = (const float*)d_in[7];
    const float* Wr1 = (const float*)d_in[8];
    const float* Wl2 = (const float*)d_in[9];
    const float* bl2 = (const float*)d_in[10];
    const float* Wr2 = (const float*)d_in[11];
    const float* W1  = (const float*)d_in[12];
    const float* b1  = (const float*)d_in[13];
    const float* W2  = (const float*)d_in[14];
    const float* b2  = (const float*)d_in[15];
    const float* W3  = (const float*)d_in[16];
    const float* b3  = (const float*)d_in[17];
    float* out = (float*)d_out;

    float *p_mean, *p_h1, *p_h2, *p_h3;
    cudaGetSymbolAddress((void**)&p_mean, g_mean);
    cudaGetSymbolAddress((void**)&p_h1, g_h1);
    cudaGetSymbolAddress((void**)&p_h2, g_h2);
    cudaGetSymbolAddress((void**)&p_h3, g_h3);

    const int TB = 256;
    int nb = (NN + TB - 1) / TB;
    int eb = (NE + TB - 1) / TB;
    int wb = (NN + (TB / 32) - 1) / (TB / 32);  // warp-per-node blocks (agg)

    // Persistent single-wave grids (148 SMs):
    const int GEMM32_BLKS = 888;  // 6 blocks/SM, 16KB smem
    const int GEMM64_BLKS = 592;  // 4 blocks/SM, 32KB smem
    const int EDGE_BLKS   = 592;  // 4 blocks/SM, 45.3KB smem

    // CSR build
    zero_cnt_kernel<<<nb, TB>>>();
    hist_kernel<<<eb, TB>>>(dstv);
    scan_local_kernel<<<25, 1024>>>();
    scan_spine_kernel<<<1, 32>>>();
    scan_add_kernel<<<25, 1024>>>();
    fill_kernel<<<eb, TB>>>(srcv, dstv);

    // Layer 0
    agg_kernel<32><<<wb, TB>>>(x, p_mean);
    sage_gemm_kernel<32, true><<<GEMM32_BLKS, TB>>>(p_mean, x, Wl0, bl0, Wr0, p_h1);
    // Layer 1
    agg_kernel<64><<<wb, TB>>>(p_h1, p_mean);
    sage_gemm_kernel<64, true><<<GEMM64_BLKS, TB>>>(p_mean, p_h1, Wl1, bl1, Wr1, p_h2);
    // Layer 2 (no relu)
    agg_kernel<64><<<wb, TB>>>(p_h2, p_mean);
    sage_gemm_kernel<64, false><<<GEMM64_BLKS, TB>>>(p_mean, p_h2, Wl2, bl2, Wr2, p_h3);

    // Edge predictor
    uv_kernel<<<GEMM64_BLKS, TB>>>(W1, b1);
    edge_kernel<<<EDGE_BLKS, 128>>>(srcv, dstv, eattr, W1, W2, b2, W3, b3, out);
}